// round 2
// baseline (speedup 1.0000x reference)
#include <cuda_runtime.h>
#include <math.h>

#define NROWS 8192
#define DIM   128
#define MFEAT 128
#define NB    64

#define PHI_EPS  1e-4f
#define NORM_EPS 1e-8f
#define INV_D4   0.29730177875068026f   // 128^-0.25
#define INV_SQM  0.08838834764831845f   // 1/sqrt(128)

typedef unsigned long long ull;

// ---- device scratch (no allocs allowed) ----
__device__ float g_Qp[NROWS * MFEAT];
__device__ float g_UK[NROWS * MFEAT];
__device__ float g_hK[NROWS];
__device__ float g_Kp[NROWS * MFEAT];
__device__ float g_S[NB * MFEAT * DIM];
__device__ float g_KsumP[4 * NB * MFEAT];   // 4 partial sums per segment
__device__ int   g_segmax[NB];              // float bits, init 0 == clamp at 0.0f
__device__ int   g_segstart[NB];
__device__ int   g_segend[NB];
__device__ int   g_is64;

// ---- packed f32x2 helpers (Blackwell) ----
__device__ __forceinline__ ull pack2(float x, float y) {
    ull r; asm("mov.b64 %0, {%1, %2};" : "=l"(r) : "f"(x), "f"(y)); return r;
}
__device__ __forceinline__ void unpack2(ull v, float& x, float& y) {
    asm("mov.b64 {%0, %1}, %2;" : "=f"(x), "=f"(y) : "l"(v));
}
__device__ __forceinline__ ull ffma2(ull a, ull b, ull c) {
    ull d; asm("fma.rn.f32x2 %0, %1, %2, %3;" : "=l"(d) : "l"(a), "l"(b), "l"(c));
    return d;
}

// batch_seg may be int32 or int64 depending on jax x64 config.
__device__ __forceinline__ int get_seg(const int* __restrict__ segp, int i) {
    return g_is64 ? segp[2 * i] : segp[i];
}

// Detect int64 vs int32 + init segment tables.
__global__ void init_kernel(const int* __restrict__ segp) {
    int t = threadIdx.x;
    if (t == 0)
        g_is64 = (segp[4097] == 0 && segp[4099] == 0 && segp[4101] == 0) ? 1 : 0;
    if (t < NB) {
        g_segmax[t]   = 0;       // float 0.0f bits
        g_segstart[t] = NROWS;
        g_segend[t]   = 0;
    }
}

__global__ void bounds_kernel(const int* __restrict__ segp) {
    int i = blockIdx.x * blockDim.x + threadIdx.x;
    if (i < NROWS) {
        int s = get_seg(segp, i);
        atomicMin(&g_segstart[s], i);
        atomicMax(&g_segend[s], i + 1);
    }
}

// ---------------------------------------------------------------------------
// U = (x * INV_D4) @ omega ; per-row h and max. 16 rows per block, 128 thr.
// Row pairs packed into f32x2; omega chunk register-resident via LDG.
// ---------------------------------------------------------------------------
template <bool IS_Q>
__global__ void __launch_bounds__(128)
u_kernel(const float* __restrict__ X, const float* __restrict__ omega,
         const int* __restrict__ segp)
{
    __shared__ __align__(16) float xs2f[8][MFEAT][2];  // [rowpair][k][which]
    __shared__ float red_h[16][4];
    __shared__ float red_m[16][4];
    __shared__ float hfin[16], mfin[16];

    int tid  = threadIdx.x;
    int lane = tid & 31;
    int wrp  = tid >> 5;
    int row0 = blockIdx.x * 16;

    float xv[16];
#pragma unroll
    for (int r = 0; r < 16; r++) {
        float v = X[(row0 + r) * DIM + tid] * INV_D4;
        xs2f[r >> 1][tid][r & 1] = v;
        xv[r] = v;
    }
    __syncthreads();

    ull acc2[8];
#pragma unroll
    for (int rp = 0; rp < 8; rp++) acc2[rp] = 0ull;

#pragma unroll
    for (int kc = 0; kc < 4; kc++) {
#pragma unroll
        for (int ks = 0; ks < 4; ks++) {
            int k0 = kc * 32 + ks * 8;
            ull wd[8];
#pragma unroll
            for (int j = 0; j < 8; j++) {
                float w = omega[(k0 + j) * MFEAT + tid];
                wd[j] = pack2(w, w);
            }
#pragma unroll
            for (int rp = 0; rp < 8; rp++) {
                const ulonglong2* xp =
                    (const ulonglong2*)&xs2f[rp][k0][0];
#pragma unroll
                for (int j2 = 0; j2 < 4; j2++) {
                    ulonglong2 xq = xp[j2];
                    acc2[rp] = ffma2(xq.x, wd[2 * j2],     acc2[rp]);
                    acc2[rp] = ffma2(xq.y, wd[2 * j2 + 1], acc2[rp]);
                }
            }
        }
    }

    // per-row reductions: sum(x'^2) and max over m of U
#pragma unroll
    for (int rp = 0; rp < 8; rp++) {
        float u0, u1;
        unpack2(acc2[rp], u0, u1);
#pragma unroll
        for (int half = 0; half < 2; half++) {
            int r = 2 * rp + half;
            float hs = xv[r] * xv[r];
            float mx = half ? u1 : u0;
#pragma unroll
            for (int o = 16; o > 0; o >>= 1) {
                hs += __shfl_xor_sync(0xffffffffu, hs, o);
                mx = fmaxf(mx, __shfl_xor_sync(0xffffffffu, mx, o));
            }
            if (lane == 0) { red_h[r][wrp] = hs; red_m[r][wrp] = mx; }
        }
    }
    __syncthreads();
    if (tid < 16) {
        float hs = red_h[tid][0] + red_h[tid][1] + red_h[tid][2] + red_h[tid][3];
        float mx = fmaxf(fmaxf(red_m[tid][0], red_m[tid][1]),
                         fmaxf(red_m[tid][2], red_m[tid][3]));
        hfin[tid] = 0.5f * hs;   // h = 0.5 * sum((x/d^0.25)^2)
        mfin[tid] = mx;
        if (!IS_Q) {
            int row = row0 + tid;
            g_hK[row] = 0.5f * hs;
            int s = get_seg(segp, row);
            atomicMax(&g_segmax[s], __float_as_int(mx));
        }
    }
    __syncthreads();

#pragma unroll
    for (int rp = 0; rp < 8; rp++) {
        float u0, u1;
        unpack2(acc2[rp], u0, u1);
        int r0 = 2 * rp, r1 = 2 * rp + 1;
        if (IS_Q) {
            g_Qp[(row0 + r0) * MFEAT + tid] =
                (__expf(u0 - hfin[r0] - mfin[r0]) + PHI_EPS) * INV_SQM;
            g_Qp[(row0 + r1) * MFEAT + tid] =
                (__expf(u1 - hfin[r1] - mfin[r1]) + PHI_EPS) * INV_SQM;
        } else {
            g_UK[(row0 + r0) * MFEAT + tid] = u0;
            g_UK[(row0 + r1) * MFEAT + tid] = u1;
        }
    }
}

// ---------------------------------------------------------------------------
// Kp = (exp(U_K - h - segmax) + eps)/sqrt(m), fused with partial Ksum.
// grid (4 row-chunks, NB)
// ---------------------------------------------------------------------------
__global__ void __launch_bounds__(128)
kp_ksum_kernel()
{
    int c = blockIdx.x;   // 0..3
    int b = blockIdx.y;   // 0..63
    int tid = threadIdx.x;
    int rs = g_segstart[b], re = g_segend[b];
    int len = re - rs;
    float smax = __int_as_float(g_segmax[b]);

    float s = 0.0f;
    if (len > 0) {
        int r0 = rs + (len * c) / 4;
        int r1 = rs + (len * (c + 1)) / 4;
#pragma unroll 2
        for (int row = r0; row < r1; row++) {
            float u = g_UK[row * MFEAT + tid];
            float h = g_hK[row];
            float kp = (__expf(u - h - smax) + PHI_EPS) * INV_SQM;
            g_Kp[row * MFEAT + tid] = kp;
            s += kp;
        }
    }
    g_KsumP[c * NB * MFEAT + b * MFEAT + tid] = s;
}

// ---------------------------------------------------------------------------
// S[b][m][d] = sum over segment rows of Kp[row][m] * V[row][d]
// grid (4 m-tiles of 32, NB). Kp chunk broadcast via uniform-address LDG.
// ---------------------------------------------------------------------------
__global__ void __launch_bounds__(128)
s_kernel(const float* __restrict__ V)
{
    int mt = blockIdx.x;      // 0..3
    int b  = blockIdx.y;      // 0..63
    int tid = threadIdx.x;
    int rs = g_segstart[b], re = g_segend[b];

    ull acc2[16];
#pragma unroll
    for (int j = 0; j < 16; j++) acc2[j] = 0ull;

    for (int row = rs; row < re; row++) {
        const ulonglong2* kp2 =
            (const ulonglong2*)(g_Kp + row * MFEAT + mt * 32);
        float v = V[row * DIM + tid];
        ull vd = pack2(v, v);
#pragma unroll
        for (int j2 = 0; j2 < 8; j2++) {
            ulonglong2 kk = kp2[j2];
            acc2[2 * j2]     = ffma2(kk.x, vd, acc2[2 * j2]);
            acc2[2 * j2 + 1] = ffma2(kk.y, vd, acc2[2 * j2 + 1]);
        }
    }
#pragma unroll
    for (int j = 0; j < 16; j++) {
        float a0, a1;
        unpack2(acc2[j], a0, a1);
        g_S[(b * MFEAT + mt * 32 + 2 * j)     * DIM + tid] = a0;
        g_S[(b * MFEAT + mt * 32 + 2 * j + 1) * DIM + tid] = a1;
    }
}

// ---------------------------------------------------------------------------
// out[i][d] = (Qp[i] . S[seg][:, d]) / (Qp[i] . Ksum[seg] + eps)
// 16 rows per block; S chunk held in registers, reused across 16 rows.
// ---------------------------------------------------------------------------
__global__ void __launch_bounds__(128)
out_kernel(const int* __restrict__ segp, float* __restrict__ out)
{
    __shared__ __align__(16) float qs2f[8][MFEAT][2];  // [rowpair][m][which]
    __shared__ int   segs[16];
    __shared__ float norms[16];

    int tid  = threadIdx.x;
    int lane = tid & 31;
    int wrp  = tid >> 5;
    int row0 = blockIdx.x * 16;

#pragma unroll
    for (int r = 0; r < 16; r++)
        qs2f[r >> 1][tid][r & 1] = g_Qp[(row0 + r) * MFEAT + tid];
    if (tid < 16) segs[tid] = get_seg(segp, row0 + tid);
    __syncthreads();

    // norms: warp w handles rows 4w..4w+3
#pragma unroll
    for (int rr = 0; rr < 4; rr++) {
        int r = wrp * 4 + rr;
        int s = segs[r];
        float p = 0.0f;
#pragma unroll
        for (int c = 0; c < 4; c++) {
            int m = c * 32 + lane;
            float q  = qs2f[r >> 1][m][r & 1];
            float ks = g_KsumP[0 * NB * MFEAT + s * MFEAT + m]
                     + g_KsumP[1 * NB * MFEAT + s * MFEAT + m]
                     + g_KsumP[2 * NB * MFEAT + s * MFEAT + m]
                     + g_KsumP[3 * NB * MFEAT + s * MFEAT + m];
            p = fmaf(q, ks, p);
        }
#pragma unroll
        for (int o = 16; o > 0; o >>= 1)
            p += __shfl_xor_sync(0xffffffffu, p, o);
        if (lane == 0) norms[r] = p + NORM_EPS;
    }
    __syncthreads();

    bool same = (segs[0] == segs[15]);   // sorted -> sufficient

    if (same) {
        const float* Srow = g_S + segs[0] * (MFEAT * DIM);
        ull acc2[8];
#pragma unroll
        for (int rp = 0; rp < 8; rp++) acc2[rp] = 0ull;

#pragma unroll
        for (int mc = 0; mc < 4; mc++) {
#pragma unroll
            for (int ms = 0; ms < 4; ms++) {
                int m0 = mc * 32 + ms * 8;
                ull sd[8];
#pragma unroll
                for (int j = 0; j < 8; j++) {
                    float sv = Srow[(m0 + j) * DIM + tid];
                    sd[j] = pack2(sv, sv);
                }
#pragma unroll
                for (int rp = 0; rp < 8; rp++) {
                    const ulonglong2* qp2 =
                        (const ulonglong2*)&qs2f[rp][m0][0];
#pragma unroll
                    for (int j2 = 0; j2 < 4; j2++) {
                        ulonglong2 qq = qp2[j2];
                        acc2[rp] = ffma2(qq.x, sd[2 * j2],     acc2[rp]);
                        acc2[rp] = ffma2(qq.y, sd[2 * j2 + 1], acc2[rp]);
                    }
                }
            }
        }
#pragma unroll
        for (int rp = 0; rp < 8; rp++) {
            float a0, a1;
            unpack2(acc2[rp], a0, a1);
            out[(row0 + 2 * rp)     * DIM + tid] = a0 / norms[2 * rp];
            out[(row0 + 2 * rp + 1) * DIM + tid] = a1 / norms[2 * rp + 1];
        }
    } else {
        // boundary block (rare): per-row direct accumulation
#pragma unroll
        for (int r = 0; r < 16; r++) {
            const float* Srow = g_S + segs[r] * (MFEAT * DIM);
            float a = 0.0f;
#pragma unroll 8
            for (int m = 0; m < MFEAT; m++)
                a = fmaf(qs2f[r >> 1][m][r & 1], Srow[m * DIM + tid], a);
            out[(row0 + r) * DIM + tid] = a / norms[r];
        }
    }
}

extern "C" void kernel_launch(void* const* d_in, const int* in_sizes, int n_in,
                              void* d_out, int out_size)
{
    const float* Q     = (const float*)d_in[0];
    const float* K     = (const float*)d_in[1];
    const float* V     = (const float*)d_in[2];
    const float* omega = (const float*)d_in[3];
    const int*   seg   = (const int*)d_in[4];
    float* out = (float*)d_out;

    init_kernel<<<1, 64>>>(seg);
    bounds_kernel<<<(NROWS + 255) / 256, 256>>>(seg);

    u_kernel<true><<<NROWS / 16, 128>>>(Q, omega, seg);
    u_kernel<false><<<NROWS / 16, 128>>>(K, omega, seg);

    kp_ksum_kernel<<<dim3(4, NB), 128>>>();
    s_kernel<<<dim3(4, NB), 128>>>(V);

    out_kernel<<<NROWS / 16, 128>>>(seg, out);
}

// round 3
// speedup vs baseline: 1.2704x; 1.2704x over previous
#include <cuda_runtime.h>
#include <math.h>

#define NROWS 8192
#define DIM   128
#define MFEAT 128
#define NB    64

#define PHI_EPS  1e-4f
#define NORM_EPS 1e-8f
#define INV_D4   0.29730177875068026f   // 128^-0.25
#define INV_SQM  0.08838834764831845f   // 1/sqrt(128)

typedef unsigned long long ull;

// ---- device scratch (no allocs allowed) ----
__device__ float g_Qp[NROWS * MFEAT];
__device__ float g_UK[NROWS * MFEAT];
__device__ float g_hK[NROWS];
__device__ float g_Kp[NROWS * MFEAT];
__device__ float g_S[NB * MFEAT * DIM];
__device__ float g_KsumP[4 * NB * MFEAT];   // 4 partial sums per segment
__device__ int   g_segmax[NB];              // float bits, init 0 == clamp at 0.0f
__device__ int   g_segstart[NB];
__device__ int   g_segend[NB];
__device__ int   g_is64;

// ---- packed f32x2 helpers (Blackwell) ----
__device__ __forceinline__ ull pack2(float x, float y) {
    ull r; asm("mov.b64 %0, {%1, %2};" : "=l"(r) : "f"(x), "f"(y)); return r;
}
__device__ __forceinline__ void unpack2(ull v, float& x, float& y) {
    asm("mov.b64 {%0, %1}, %2;" : "=f"(x), "=f"(y) : "l"(v));
}
__device__ __forceinline__ ull ffma2(ull a, ull b, ull c) {
    ull d; asm("fma.rn.f32x2 %0, %1, %2, %3;" : "=l"(d) : "l"(a), "l"(b), "l"(c));
    return d;
}

// batch_seg may be int32 or int64 depending on jax x64 config.
__device__ __forceinline__ int get_seg(const int* __restrict__ segp, int i) {
    return g_is64 ? segp[2 * i] : segp[i];
}

// Detect int64 vs int32 + init segment tables.
__global__ void init_kernel(const int* __restrict__ segp) {
    int t = threadIdx.x;
    if (t == 0)
        g_is64 = (segp[4097] == 0 && segp[4099] == 0 && segp[4101] == 0) ? 1 : 0;
    if (t < NB) {
        g_segmax[t]   = 0;       // float 0.0f bits
        g_segstart[t] = NROWS;
        g_segend[t]   = 0;
    }
}

__global__ void bounds_kernel(const int* __restrict__ segp) {
    int i = blockIdx.x * blockDim.x + threadIdx.x;
    if (i < NROWS) {
        int s = get_seg(segp, i);
        atomicMin(&g_segstart[s], i);
        atomicMax(&g_segend[s], i + 1);
    }
}

// ---------------------------------------------------------------------------
// U = (x * INV_D4) @ omega ; per-row h and max(U).
// Register-tiled: 256 threads, block computes 32 rows x 128 m.
// Thread (wrp, lane): rows wrp*4..wrp*4+3, m = lane + 32*{0..3}.
// ---------------------------------------------------------------------------
template <bool IS_Q>
__global__ void __launch_bounds__(256)
u_kernel(const float* __restrict__ X, const float* __restrict__ omega,
         const int* __restrict__ segp)
{
    __shared__ __align__(16) float xs[128][32];   // [k][row], scaled by INV_D4
    __shared__ __align__(16) float ws[32][128];   // [kk][m] omega chunk
    __shared__ float hsum[32];

    int t    = threadIdx.x;
    int lane = t & 31;
    int wrp  = t >> 5;            // 0..7, warp owns rows wrp*4..wrp*4+3
    int row0 = blockIdx.x * 32;

    if (t < 32) hsum[t] = 0.0f;
    __syncthreads();

    // Load X transposed into xs, accumulate sum of squares per row.
    {
        int row = t & 31;
        int kqb = t >> 5;
        float ss = 0.0f;
#pragma unroll
        for (int it = 0; it < 4; it++) {
            int kq = kqb + 8 * it;
            float4 xv = *(const float4*)(X + (row0 + row) * DIM + kq * 4);
            xv.x *= INV_D4; xv.y *= INV_D4; xv.z *= INV_D4; xv.w *= INV_D4;
            xs[kq * 4 + 0][row] = xv.x;
            xs[kq * 4 + 1][row] = xv.y;
            xs[kq * 4 + 2][row] = xv.z;
            xs[kq * 4 + 3][row] = xv.w;
            ss += xv.x * xv.x + xv.y * xv.y + xv.z * xv.z + xv.w * xv.w;
        }
        atomicAdd(&hsum[row], ss);
    }

    ull acc[4][2];                // [mi][rowpair]
#pragma unroll
    for (int mi = 0; mi < 4; mi++) { acc[mi][0] = 0ull; acc[mi][1] = 0ull; }

#pragma unroll 1
    for (int kc = 0; kc < 4; kc++) {
        __syncthreads();
        // load omega chunk [32 k][128 m]
        {
            int m4 = t & 31, kkb = t >> 5;
#pragma unroll
            for (int it = 0; it < 4; it++) {
                int kk = kkb + 8 * it;
                *(float4*)&ws[kk][m4 * 4] =
                    *(const float4*)(omega + (kc * 32 + kk) * MFEAT + m4 * 4);
            }
        }
        __syncthreads();
#pragma unroll
        for (int kk = 0; kk < 32; kk++) {
            int k = kc * 32 + kk;
            float4 xq = *(const float4*)&xs[k][wrp * 4];   // 4 rows, broadcast
            ull x01 = pack2(xq.x, xq.y);
            ull x23 = pack2(xq.z, xq.w);
#pragma unroll
            for (int mi = 0; mi < 4; mi++) {
                float w = ws[kk][lane + 32 * mi];
                ull wd = pack2(w, w);
                acc[mi][0] = ffma2(x01, wd, acc[mi][0]);
                acc[mi][1] = ffma2(x23, wd, acc[mi][1]);
            }
        }
    }
    __syncthreads();   // hsum atomics long done; ensure visibility

    // unpack to u[rowj][mi]
    float u[4][4];
#pragma unroll
    for (int mi = 0; mi < 4; mi++) {
        unpack2(acc[mi][0], u[0][mi], u[1][mi]);
        unpack2(acc[mi][1], u[2][mi], u[3][mi]);
    }

#pragma unroll
    for (int j = 0; j < 4; j++) {
        int rloc = wrp * 4 + j;
        int row  = row0 + rloc;
        float mx = fmaxf(fmaxf(u[j][0], u[j][1]), fmaxf(u[j][2], u[j][3]));
#pragma unroll
        for (int o = 16; o > 0; o >>= 1)
            mx = fmaxf(mx, __shfl_xor_sync(0xffffffffu, mx, o));
        float h = 0.5f * hsum[rloc];

        if (IS_Q) {
#pragma unroll
            for (int mi = 0; mi < 4; mi++)
                g_Qp[row * MFEAT + lane + 32 * mi] =
                    (__expf(u[j][mi] - h - mx) + PHI_EPS) * INV_SQM;
        } else {
#pragma unroll
            for (int mi = 0; mi < 4; mi++)
                g_UK[row * MFEAT + lane + 32 * mi] = u[j][mi];
            if (lane == 0) {
                g_hK[row] = h;
                int s = get_seg(segp, row);
                atomicMax(&g_segmax[s], __float_as_int(mx));
            }
        }
    }
}

// ---------------------------------------------------------------------------
// Kp = (exp(U_K - h - segmax) + eps)/sqrt(m), fused with partial Ksum.
// grid (4 row-chunks, NB)
// ---------------------------------------------------------------------------
__global__ void __launch_bounds__(128)
kp_ksum_kernel()
{
    int c = blockIdx.x;   // 0..3
    int b = blockIdx.y;   // 0..63
    int tid = threadIdx.x;
    int rs = g_segstart[b], re = g_segend[b];
    int len = re - rs;
    float smax = __int_as_float(g_segmax[b]);

    float s = 0.0f;
    if (len > 0) {
        int r0 = rs + (len * c) / 4;
        int r1 = rs + (len * (c + 1)) / 4;
#pragma unroll 2
        for (int row = r0; row < r1; row++) {
            float u = g_UK[row * MFEAT + tid];
            float h = g_hK[row];
            float kp = (__expf(u - h - smax) + PHI_EPS) * INV_SQM;
            g_Kp[row * MFEAT + tid] = kp;
            s += kp;
        }
    }
    g_KsumP[c * NB * MFEAT + b * MFEAT + tid] = s;
}

// ---------------------------------------------------------------------------
// S[b][m][d] = sum over segment rows of Kp[row][m] * V[row][d]
// grid (4 m-tiles of 32, NB), 128 threads (tid = d).
// Kp staged in smem per 16-row chunk; V via direct LDG (MLP across the chunk).
// ---------------------------------------------------------------------------
__global__ void __launch_bounds__(128)
s_kernel(const float* __restrict__ V)
{
    int mt  = blockIdx.x;     // 0..3
    int b   = blockIdx.y;     // 0..63
    int tid = threadIdx.x;
    int rs = g_segstart[b], re = g_segend[b];

    __shared__ __align__(16) float kpc[16][32];

    ull acc[16];
#pragma unroll
    for (int j = 0; j < 16; j++) acc[j] = 0ull;

    int row = rs;
    for (; row + 16 <= re; row += 16) {
        {
            int rr = tid >> 3, c4 = tid & 7;
            *(float4*)&kpc[rr][c4 * 4] =
                *(const float4*)(g_Kp + (row + rr) * MFEAT + mt * 32 + c4 * 4);
        }
        __syncthreads();
#pragma unroll
        for (int rr = 0; rr < 16; rr++) {
            float v = V[(row + rr) * DIM + tid];
            ull vd = pack2(v, v);
            const ulonglong2* kp2 = (const ulonglong2*)&kpc[rr][0];
#pragma unroll
            for (int j2 = 0; j2 < 8; j2++) {
                ulonglong2 kk2 = kp2[j2];
                acc[2 * j2]     = ffma2(kk2.x, vd, acc[2 * j2]);
                acc[2 * j2 + 1] = ffma2(kk2.y, vd, acc[2 * j2 + 1]);
            }
        }
        __syncthreads();
    }
    // tail rows (< 16)
    for (; row < re; row++) {
        float v = V[row * DIM + tid];
        ull vd = pack2(v, v);
        const ulonglong2* kp2 =
            (const ulonglong2*)(g_Kp + row * MFEAT + mt * 32);
#pragma unroll
        for (int j2 = 0; j2 < 8; j2++) {
            ulonglong2 kk2 = kp2[j2];
            acc[2 * j2]     = ffma2(kk2.x, vd, acc[2 * j2]);
            acc[2 * j2 + 1] = ffma2(kk2.y, vd, acc[2 * j2 + 1]);
        }
    }

#pragma unroll
    for (int j = 0; j < 16; j++) {
        float a0, a1;
        unpack2(acc[j], a0, a1);
        g_S[(b * MFEAT + mt * 32 + 2 * j)     * DIM + tid] = a0;
        g_S[(b * MFEAT + mt * 32 + 2 * j + 1) * DIM + tid] = a1;
    }
}

// ---------------------------------------------------------------------------
// out[i][d] = (Qp[i] . S[seg][:, d]) / (Qp[i] . Ksum[seg] + eps)
// 16 rows per block; S chunk held in registers, reused across 16 rows.
// ---------------------------------------------------------------------------
__global__ void __launch_bounds__(128)
out_kernel(const int* __restrict__ segp, float* __restrict__ out)
{
    __shared__ __align__(16) float qs2f[8][MFEAT][2];  // [rowpair][m][which]
    __shared__ int   segs[16];
    __shared__ float norms[16];

    int tid  = threadIdx.x;
    int lane = tid & 31;
    int wrp  = tid >> 5;
    int row0 = blockIdx.x * 16;

#pragma unroll
    for (int r = 0; r < 16; r++)
        qs2f[r >> 1][tid][r & 1] = g_Qp[(row0 + r) * MFEAT + tid];
    if (tid < 16) segs[tid] = get_seg(segp, row0 + tid);
    __syncthreads();

    // norms: warp w handles rows 4w..4w+3
#pragma unroll
    for (int rr = 0; rr < 4; rr++) {
        int r = wrp * 4 + rr;
        int s = segs[r];
        float p = 0.0f;
#pragma unroll
        for (int c = 0; c < 4; c++) {
            int m = c * 32 + lane;
            float q  = qs2f[r >> 1][m][r & 1];
            float ks = g_KsumP[0 * NB * MFEAT + s * MFEAT + m]
                     + g_KsumP[1 * NB * MFEAT + s * MFEAT + m]
                     + g_KsumP[2 * NB * MFEAT + s * MFEAT + m]
                     + g_KsumP[3 * NB * MFEAT + s * MFEAT + m];
            p = fmaf(q, ks, p);
        }
#pragma unroll
        for (int o = 16; o > 0; o >>= 1)
            p += __shfl_xor_sync(0xffffffffu, p, o);
        if (lane == 0) norms[r] = p + NORM_EPS;
    }
    __syncthreads();

    bool same = (segs[0] == segs[15]);   // sorted -> sufficient

    if (same) {
        const float* Srow = g_S + segs[0] * (MFEAT * DIM);
        ull acc2[8];
#pragma unroll
        for (int rp = 0; rp < 8; rp++) acc2[rp] = 0ull;

#pragma unroll
        for (int mc = 0; mc < 4; mc++) {
#pragma unroll
            for (int ms = 0; ms < 4; ms++) {
                int m0 = mc * 32 + ms * 8;
                ull sd[8];
#pragma unroll
                for (int j = 0; j < 8; j++) {
                    float sv = Srow[(m0 + j) * DIM + tid];
                    sd[j] = pack2(sv, sv);
                }
#pragma unroll
                for (int rp = 0; rp < 8; rp++) {
                    const ulonglong2* qp2 =
                        (const ulonglong2*)&qs2f[rp][m0][0];
#pragma unroll
                    for (int j2 = 0; j2 < 4; j2++) {
                        ulonglong2 qq = qp2[j2];
                        acc2[rp] = ffma2(qq.x, sd[2 * j2],     acc2[rp]);
                        acc2[rp] = ffma2(qq.y, sd[2 * j2 + 1], acc2[rp]);
                    }
                }
            }
        }
#pragma unroll
        for (int rp = 0; rp < 8; rp++) {
            float a0, a1;
            unpack2(acc2[rp], a0, a1);
            out[(row0 + 2 * rp)     * DIM + tid] = a0 / norms[2 * rp];
            out[(row0 + 2 * rp + 1) * DIM + tid] = a1 / norms[2 * rp + 1];
        }
    } else {
        // boundary block (rare): per-row direct accumulation
#pragma unroll
        for (int r = 0; r < 16; r++) {
            const float* Srow = g_S + segs[r] * (MFEAT * DIM);
            float a = 0.0f;
#pragma unroll 8
            for (int m = 0; m < MFEAT; m++)
                a = fmaf(qs2f[r >> 1][m][r & 1], Srow[m * DIM + tid], a);
            out[(row0 + r) * DIM + tid] = a / norms[r];
        }
    }
}

extern "C" void kernel_launch(void* const* d_in, const int* in_sizes, int n_in,
                              void* d_out, int out_size)
{
    const float* Q     = (const float*)d_in[0];
    const float* K     = (const float*)d_in[1];
    const float* V     = (const float*)d_in[2];
    const float* omega = (const float*)d_in[3];
    const int*   seg   = (const int*)d_in[4];
    float* out = (float*)d_out;

    init_kernel<<<1, 64>>>(seg);
    bounds_kernel<<<(NROWS + 255) / 256, 256>>>(seg);

    u_kernel<true><<<NROWS / 32, 256>>>(Q, omega, seg);
    u_kernel<false><<<NROWS / 32, 256>>>(K, omega, seg);

    kp_ksum_kernel<<<dim3(4, NB), 128>>>();
    s_kernel<<<dim3(4, NB), 128>>>(V);

    out_kernel<<<NROWS / 16, 128>>>(seg, out);
}

// round 4
// speedup vs baseline: 1.5552x; 1.2242x over previous
#include <cuda_runtime.h>
#include <math.h>

#define NROWS 8192
#define DIM   128
#define MFEAT 128
#define NB    64

#define PHI_EPS  1e-4f
#define NORM_EPS 1e-8f
#define INV_D4   0.29730177875068026f   // 128^-0.25
#define INV_SQM  0.08838834764831845f   // 1/sqrt(128)

typedef unsigned long long ull;

// ---- device scratch (no allocs allowed) ----
__device__ float g_Qp[NROWS * MFEAT];
__device__ float g_EK[NROWS * MFEAT];       // exp(U_K - h)
__device__ float g_S[NB * MFEAT * DIM];
__device__ float g_Ksum[NB * MFEAT];
__device__ int   g_segmax[NB];              // float bits, init 0 == clamp at 0.0f
__device__ int   g_segstart[NB];
__device__ int   g_segend[NB];
__device__ int   g_is64;

// ---- packed f32x2 helpers (Blackwell) ----
__device__ __forceinline__ ull pack2(float x, float y) {
    ull r; asm("mov.b64 %0, {%1, %2};" : "=l"(r) : "f"(x), "f"(y)); return r;
}
__device__ __forceinline__ void unpack2(ull v, float& x, float& y) {
    asm("mov.b64 {%0, %1}, %2;" : "=f"(x), "=f"(y) : "l"(v));
}
__device__ __forceinline__ ull ffma2(ull a, ull b, ull c) {
    ull d; asm("fma.rn.f32x2 %0, %1, %2, %3;" : "=l"(d) : "l"(a), "l"(b), "l"(c));
    return d;
}

__device__ __forceinline__ int get_seg(const int* __restrict__ segp, int i) {
    return g_is64 ? segp[2 * i] : segp[i];
}

// ---------------------------------------------------------------------------
// Segment bounds from sorted batch_seg (boundary scan, no atomics) + segmax
// init + int64/int32 detection.
// ---------------------------------------------------------------------------
__global__ void __launch_bounds__(256)
bounds_kernel(const int* __restrict__ segp)
{
    __shared__ int s_is64;
    if (threadIdx.x == 0) {
        s_is64 = (segp[4097] == 0 && segp[4099] == 0 && segp[4101] == 0) ? 1 : 0;
        if (blockIdx.x == 0) g_is64 = s_is64;
    }
    __syncthreads();
    int is64 = s_is64;

    if (blockIdx.x == 0 && threadIdx.x < NB)
        g_segmax[threadIdx.x] = 0;          // float 0.0f bits == clamp at 0

    int i = blockIdx.x * blockDim.x + threadIdx.x;
    if (i < NROWS) {
        int cur  = is64 ? segp[2 * i] : segp[i];
        int prev = (i == 0) ? -1
                            : (is64 ? segp[2 * (i - 1)] : segp[i - 1]);
        for (int b = prev + 1; b <= cur; b++) g_segstart[b] = i;
        int nxt = (i == NROWS - 1) ? NB
                                   : (is64 ? segp[2 * (i + 1)] : segp[i + 1]);
        for (int b = cur; b < nxt; b++) g_segend[b] = i + 1;
        if (i == NROWS - 1)
            for (int b = cur + 1; b < NB; b++) g_segstart[b] = NROWS;
    }
}

// ---------------------------------------------------------------------------
// Fused Q/K feature kernel. grid = 2*(NROWS/32); first half Q, second half K.
// Block computes 32 rows x 128 m. Thread (wrp, lane): rows wrp*4..+3,
// m = lane + 32*{0..3}. omega stored duplicated (w,w) in smem -> LDS.64
// feeds FFMA2 operand b directly.
//   Q: Qp = (exp(U - h - rowmax) + eps)/sqrt(m)
//   K: E  = exp(U - h); segmax via atomicMax (clamped at 0 by init)
// ---------------------------------------------------------------------------
__global__ void __launch_bounds__(256)
u_kernel(const float* __restrict__ Qin, const float* __restrict__ Kin,
         const float* __restrict__ omega, const int* __restrict__ segp)
{
    __shared__ __align__(16) float xs[128][32];      // [k][row]
    __shared__ __align__(16) float ws[16][128][2];   // [kk][m][dup]
    __shared__ float hsum[32];

    const int NBQ = NROWS / 32;
    bool isQ = blockIdx.x < NBQ;
    const float* X = isQ ? Qin : Kin;
    int row0 = (isQ ? blockIdx.x : blockIdx.x - NBQ) * 32;

    int t    = threadIdx.x;
    int lane = t & 31;
    int wrp  = t >> 5;

    if (t < 32) hsum[t] = 0.0f;
    __syncthreads();

    // Stage X transposed into xs, accumulate sum of squares per row.
    {
        int row = t & 31;
        int kqb = t >> 5;
        float ss = 0.0f;
#pragma unroll
        for (int it = 0; it < 4; it++) {
            int kq = kqb + 8 * it;
            float4 xv = *(const float4*)(X + (row0 + row) * DIM + kq * 4);
            xv.x *= INV_D4; xv.y *= INV_D4; xv.z *= INV_D4; xv.w *= INV_D4;
            xs[kq * 4 + 0][row] = xv.x;
            xs[kq * 4 + 1][row] = xv.y;
            xs[kq * 4 + 2][row] = xv.z;
            xs[kq * 4 + 3][row] = xv.w;
            ss += xv.x * xv.x + xv.y * xv.y + xv.z * xv.z + xv.w * xv.w;
        }
        atomicAdd(&hsum[row], ss);
    }

    ull acc[4][2];          // [mi][rowpair]
#pragma unroll
    for (int mi = 0; mi < 4; mi++) { acc[mi][0] = 0ull; acc[mi][1] = 0ull; }

#pragma unroll 1
    for (int kc = 0; kc < 8; kc++) {
        __syncthreads();
        // Stage omega chunk [16 kk][128 m], duplicated pairs.
        // Thread t: kk = wrp*2 + it, m = lane + 32*q  (consecutive-m STS.64)
        {
#pragma unroll
            for (int it = 0; it < 2; it++) {
                int kk = wrp * 2 + it;
#pragma unroll
                for (int q = 0; q < 4; q++) {
                    int m = lane + 32 * q;
                    float w = omega[(kc * 16 + kk) * MFEAT + m];
                    *(float2*)&ws[kk][m][0] = make_float2(w, w);
                }
            }
        }
        __syncthreads();
#pragma unroll
        for (int kk = 0; kk < 16; kk++) {
            int k = kc * 16 + kk;
            float4 xq = *(const float4*)&xs[k][wrp * 4];   // 4 rows broadcast
            ull x01 = pack2(xq.x, xq.y);
            ull x23 = pack2(xq.z, xq.w);
#pragma unroll
            for (int mi = 0; mi < 4; mi++) {
                ull wd = *(const ull*)&ws[kk][lane + 32 * mi][0];
                acc[mi][0] = ffma2(x01, wd, acc[mi][0]);
                acc[mi][1] = ffma2(x23, wd, acc[mi][1]);
            }
        }
    }
    __syncthreads();

    float u[4][4];
#pragma unroll
    for (int mi = 0; mi < 4; mi++) {
        unpack2(acc[mi][0], u[0][mi], u[1][mi]);
        unpack2(acc[mi][1], u[2][mi], u[3][mi]);
    }

#pragma unroll
    for (int j = 0; j < 4; j++) {
        int rloc = wrp * 4 + j;
        int row  = row0 + rloc;
        float mx = fmaxf(fmaxf(u[j][0], u[j][1]), fmaxf(u[j][2], u[j][3]));
#pragma unroll
        for (int o = 16; o > 0; o >>= 1)
            mx = fmaxf(mx, __shfl_xor_sync(0xffffffffu, mx, o));
        float h = 0.5f * hsum[rloc];

        if (isQ) {
#pragma unroll
            for (int mi = 0; mi < 4; mi++)
                g_Qp[row * MFEAT + lane + 32 * mi] =
                    (__expf(u[j][mi] - h - mx) + PHI_EPS) * INV_SQM;
        } else {
#pragma unroll
            for (int mi = 0; mi < 4; mi++)
                g_EK[row * MFEAT + lane + 32 * mi] = __expf(u[j][mi] - h);
            if (lane == 0) {
                int s = get_seg(segp, row);
                atomicMax(&g_segmax[s], __float_as_int(mx));
            }
        }
    }
}

// ---------------------------------------------------------------------------
// S[b][m][d] = sum_rows Kp[row][m] * V[row][d];  Ksum[b][m] = sum_rows Kp.
// Kp reconstructed on the fly: kp = fma(E, exp(-smax)/sqrt(m), eps/sqrt(m)).
// grid (8 m-tiles of 16, NB), 128 threads (tid = d). 16-row chunks staged in
// smem, next chunk's E prefetched into registers during compute.
// ---------------------------------------------------------------------------
__global__ void __launch_bounds__(128)
s_kernel(const float* __restrict__ V)
{
    int mt  = blockIdx.x;     // 0..7
    int b   = blockIdx.y;     // 0..63
    int tid = threadIdx.x;
    int rs = g_segstart[b], re = g_segend[b];
    float smax = __int_as_float(g_segmax[b]);
    float cA = __expf(-smax) * INV_SQM;
    float cB = PHI_EPS * INV_SQM;

    __shared__ __align__(16) float kpc[16][16];

    ull acc[8];
#pragma unroll
    for (int j = 0; j < 8; j++) acc[j] = 0ull;
    float ksum = 0.0f;

    int rr_s = tid >> 3;          // staging row 0..15
    int m2   = (tid & 7) * 2;     // staging m pair

    int row = rs;
    int nfull = (re - rs) >> 4;

    float2 e;
    if (nfull > 0)
        e = *(const float2*)(g_EK + (row + rr_s) * MFEAT + mt * 16 + m2);

    for (int c = 0; c < nfull; c++, row += 16) {
        float2 kp;
        kp.x = fmaf(e.x, cA, cB);
        kp.y = fmaf(e.y, cA, cB);
        *(float2*)&kpc[rr_s][m2] = kp;
        __syncthreads();
        if (c + 1 < nfull)
            e = *(const float2*)(g_EK + (row + 16 + rr_s) * MFEAT + mt * 16 + m2);
#pragma unroll
        for (int rr = 0; rr < 16; rr++) {
            float v = V[(row + rr) * DIM + tid];
            ull vd = pack2(v, v);
            const ulonglong2* kp2 = (const ulonglong2*)&kpc[rr][0];
#pragma unroll
            for (int j = 0; j < 4; j++) {
                ulonglong2 kk2 = kp2[j];
                acc[2 * j]     = ffma2(kk2.x, vd, acc[2 * j]);
                acc[2 * j + 1] = ffma2(kk2.y, vd, acc[2 * j + 1]);
            }
        }
        if (tid < 16) {
#pragma unroll
            for (int rr = 0; rr < 16; rr++) ksum += kpc[rr][tid];
        }
        __syncthreads();
    }

    // tail rows (< 16)
    int ntail = re - row;
    if (ntail > 0) {
        if (rr_s < ntail) {
            float2 et = *(const float2*)(g_EK + (row + rr_s) * MFEAT + mt * 16 + m2);
            float2 kp;
            kp.x = fmaf(et.x, cA, cB);
            kp.y = fmaf(et.y, cA, cB);
            *(float2*)&kpc[rr_s][m2] = kp;
        }
        __syncthreads();
        for (int rr = 0; rr < ntail; rr++) {
            float v = V[(row + rr) * DIM + tid];
            ull vd = pack2(v, v);
            const ulonglong2* kp2 = (const ulonglong2*)&kpc[rr][0];
#pragma unroll
            for (int j = 0; j < 4; j++) {
                ulonglong2 kk2 = kp2[j];
                acc[2 * j]     = ffma2(kk2.x, vd, acc[2 * j]);
                acc[2 * j + 1] = ffma2(kk2.y, vd, acc[2 * j + 1]);
            }
        }
        if (tid < 16)
            for (int rr = 0; rr < ntail; rr++) ksum += kpc[rr][tid];
    }

#pragma unroll
    for (int j = 0; j < 8; j++) {
        float a0, a1;
        unpack2(acc[j], a0, a1);
        g_S[(b * MFEAT + mt * 16 + 2 * j)     * DIM + tid] = a0;
        g_S[(b * MFEAT + mt * 16 + 2 * j + 1) * DIM + tid] = a1;
    }
    if (tid < 16)
        g_Ksum[b * MFEAT + mt * 16 + tid] = ksum;
}

// ---------------------------------------------------------------------------
// out[i][d] = (Qp[i] . S[seg][:, d]) / (Qp[i] . Ksum[seg] + eps)
// 16 rows per block; S chunk held in registers, reused across 16 rows.
// ---------------------------------------------------------------------------
__global__ void __launch_bounds__(128)
out_kernel(const int* __restrict__ segp, float* __restrict__ out)
{
    __shared__ __align__(16) float qs2f[8][MFEAT][2];  // [rowpair][m][which]
    __shared__ int   segs[16];
    __shared__ float norms[16];

    int tid  = threadIdx.x;
    int lane = tid & 31;
    int wrp  = tid >> 5;
    int row0 = blockIdx.x * 16;

#pragma unroll
    for (int r = 0; r < 16; r++)
        qs2f[r >> 1][tid][r & 1] = g_Qp[(row0 + r) * MFEAT + tid];
    if (tid < 16) segs[tid] = get_seg(segp, row0 + tid);
    __syncthreads();

    // norms: warp w handles rows 4w..4w+3
#pragma unroll
    for (int rr = 0; rr < 4; rr++) {
        int r = wrp * 4 + rr;
        int s = segs[r];
        float p = 0.0f;
#pragma unroll
        for (int c = 0; c < 4; c++) {
            int m = c * 32 + lane;
            float q  = qs2f[r >> 1][m][r & 1];
            float ks = g_Ksum[s * MFEAT + m];
            p = fmaf(q, ks, p);
        }
#pragma unroll
        for (int o = 16; o > 0; o >>= 1)
            p += __shfl_xor_sync(0xffffffffu, p, o);
        if (lane == 0) norms[r] = p + NORM_EPS;
    }
    __syncthreads();

    bool same = (segs[0] == segs[15]);   // sorted -> sufficient

    if (same) {
        const float* Srow = g_S + segs[0] * (MFEAT * DIM);
        ull acc2[8];
#pragma unroll
        for (int rp = 0; rp < 8; rp++) acc2[rp] = 0ull;

#pragma unroll
        for (int mc = 0; mc < 4; mc++) {
#pragma unroll
            for (int ms = 0; ms < 4; ms++) {
                int m0 = mc * 32 + ms * 8;
                ull sd[8];
#pragma unroll
                for (int j = 0; j < 8; j++) {
                    float sv = Srow[(m0 + j) * DIM + tid];
                    sd[j] = pack2(sv, sv);
                }
#pragma unroll
                for (int rp = 0; rp < 8; rp++) {
                    const ulonglong2* qp2 =
                        (const ulonglong2*)&qs2f[rp][m0][0];
#pragma unroll
                    for (int j2 = 0; j2 < 4; j2++) {
                        ulonglong2 qq = qp2[j2];
                        acc2[rp] = ffma2(qq.x, sd[2 * j2],     acc2[rp]);
                        acc2[rp] = ffma2(qq.y, sd[2 * j2 + 1], acc2[rp]);
                    }
                }
            }
        }
#pragma unroll
        for (int rp = 0; rp < 8; rp++) {
            float a0, a1;
            unpack2(acc2[rp], a0, a1);
            out[(row0 + 2 * rp)     * DIM + tid] = a0 / norms[2 * rp];
            out[(row0 + 2 * rp + 1) * DIM + tid] = a1 / norms[2 * rp + 1];
        }
    } else {
        // boundary block (rare): per-row direct accumulation
#pragma unroll
        for (int r = 0; r < 16; r++) {
            const float* Srow = g_S + segs[r] * (MFEAT * DIM);
            float a = 0.0f;
#pragma unroll 8
            for (int m = 0; m < MFEAT; m++)
                a = fmaf(qs2f[r >> 1][m][r & 1], Srow[m * DIM + tid], a);
            out[(row0 + r) * DIM + tid] = a / norms[r];
        }
    }
}

extern "C" void kernel_launch(void* const* d_in, const int* in_sizes, int n_in,
                              void* d_out, int out_size)
{
    const float* Q     = (const float*)d_in[0];
    const float* K     = (const float*)d_in[1];
    const float* V     = (const float*)d_in[2];
    const float* omega = (const float*)d_in[3];
    const int*   seg   = (const int*)d_in[4];
    float* out = (float*)d_out;

    bounds_kernel<<<NROWS / 256, 256>>>(seg);
    u_kernel<<<2 * (NROWS / 32), 256>>>(Q, K, omega, seg);
    s_kernel<<<dim3(8, NB), 128>>>(V);
    out_kernel<<<NROWS / 16, 128>>>(seg, out);
}

// round 5
// speedup vs baseline: 2.1281x; 1.3684x over previous
#include <cuda_runtime.h>
#include <math.h>

#define NROWS 8192
#define DIM   128
#define MFEAT 128
#define NB    64

#define PHI_EPS  1e-4f
#define NORM_EPS 1e-8f
#define INV_D4   0.29730177875068026f   // 128^-0.25
#define INV_SQM  0.08838834764831845f   // 1/sqrt(128)

typedef unsigned long long ull;

// ---- device scratch (no allocs allowed) ----
__device__ float g_Qp[NROWS * MFEAT];
__device__ float g_EK[NROWS * MFEAT];       // exp(U_K - h)
__device__ float g_S[NB * MFEAT * DIM];
__device__ float g_Ksum[NB * MFEAT];
__device__ int   g_segmax[NB];              // float bits, init 0 == clamp at 0.0f
__device__ int   g_segstart[NB];
__device__ int   g_segend[NB];
__device__ int   g_is64;

// ---- packed f32x2 helpers (Blackwell) ----
__device__ __forceinline__ ull pack2(float x, float y) {
    ull r; asm("mov.b64 %0, {%1, %2};" : "=l"(r) : "f"(x), "f"(y)); return r;
}
__device__ __forceinline__ void unpack2(ull v, float& x, float& y) {
    asm("mov.b64 {%0, %1}, %2;" : "=f"(x), "=f"(y) : "l"(v));
}
__device__ __forceinline__ ull ffma2(ull a, ull b, ull c) {
    ull d; asm("fma.rn.f32x2 %0, %1, %2, %3;" : "=l"(d) : "l"(a), "l"(b), "l"(c));
    return d;
}

__device__ __forceinline__ int get_seg(const int* __restrict__ segp, int i) {
    return g_is64 ? segp[2 * i] : segp[i];
}

// ---------------------------------------------------------------------------
// Segment bounds from sorted batch_seg (boundary scan, no atomics) + segmax
// init + int64/int32 detection.
// ---------------------------------------------------------------------------
__global__ void __launch_bounds__(256)
bounds_kernel(const int* __restrict__ segp)
{
    __shared__ int s_is64;
    if (threadIdx.x == 0) {
        s_is64 = (segp[4097] == 0 && segp[4099] == 0 && segp[4101] == 0) ? 1 : 0;
        if (blockIdx.x == 0) g_is64 = s_is64;
    }
    __syncthreads();
    int is64 = s_is64;

    if (blockIdx.x == 0 && threadIdx.x < NB)
        g_segmax[threadIdx.x] = 0;          // float 0.0f bits == clamp at 0

    int i = blockIdx.x * blockDim.x + threadIdx.x;
    if (i < NROWS) {
        int cur  = is64 ? segp[2 * i] : segp[i];
        int prev = (i == 0) ? -1
                            : (is64 ? segp[2 * (i - 1)] : segp[i - 1]);
        for (int b = prev + 1; b <= cur; b++) g_segstart[b] = i;
        int nxt = (i == NROWS - 1) ? NB
                                   : (is64 ? segp[2 * (i + 1)] : segp[i + 1]);
        for (int b = cur; b < nxt; b++) g_segend[b] = i + 1;
        if (i == NROWS - 1)
            for (int b = cur + 1; b < NB; b++) g_segstart[b] = NROWS;
    }
}

// ---------------------------------------------------------------------------
// Fused Q/K feature kernel. grid = 2*(NROWS/32); first half Q, second half K.
// ---------------------------------------------------------------------------
__global__ void __launch_bounds__(256)
u_kernel(const float* __restrict__ Qin, const float* __restrict__ Kin,
         const float* __restrict__ omega, const int* __restrict__ segp)
{
    __shared__ __align__(16) float xs[128][32];      // [k][row]
    __shared__ __align__(16) float ws[16][128][2];   // [kk][m][dup]
    __shared__ float hsum[32];

    const int NBQ = NROWS / 32;
    bool isQ = blockIdx.x < NBQ;
    const float* X = isQ ? Qin : Kin;
    int row0 = (isQ ? blockIdx.x : blockIdx.x - NBQ) * 32;

    int t    = threadIdx.x;
    int lane = t & 31;
    int wrp  = t >> 5;

    if (t < 32) hsum[t] = 0.0f;
    __syncthreads();

    {
        int row = t & 31;
        int kqb = t >> 5;
        float ss = 0.0f;
#pragma unroll
        for (int it = 0; it < 4; it++) {
            int kq = kqb + 8 * it;
            float4 xv = *(const float4*)(X + (row0 + row) * DIM + kq * 4);
            xv.x *= INV_D4; xv.y *= INV_D4; xv.z *= INV_D4; xv.w *= INV_D4;
            xs[kq * 4 + 0][row] = xv.x;
            xs[kq * 4 + 1][row] = xv.y;
            xs[kq * 4 + 2][row] = xv.z;
            xs[kq * 4 + 3][row] = xv.w;
            ss += xv.x * xv.x + xv.y * xv.y + xv.z * xv.z + xv.w * xv.w;
        }
        atomicAdd(&hsum[row], ss);
    }

    ull acc[4][2];          // [mi][rowpair]
#pragma unroll
    for (int mi = 0; mi < 4; mi++) { acc[mi][0] = 0ull; acc[mi][1] = 0ull; }

#pragma unroll 1
    for (int kc = 0; kc < 8; kc++) {
        __syncthreads();
        {
#pragma unroll
            for (int it = 0; it < 2; it++) {
                int kk = wrp * 2 + it;
#pragma unroll
                for (int q = 0; q < 4; q++) {
                    int m = lane + 32 * q;
                    float w = omega[(kc * 16 + kk) * MFEAT + m];
                    *(float2*)&ws[kk][m][0] = make_float2(w, w);
                }
            }
        }
        __syncthreads();
#pragma unroll
        for (int kk = 0; kk < 16; kk++) {
            int k = kc * 16 + kk;
            float4 xq = *(const float4*)&xs[k][wrp * 4];   // 4 rows broadcast
            ull x01 = pack2(xq.x, xq.y);
            ull x23 = pack2(xq.z, xq.w);
#pragma unroll
            for (int mi = 0; mi < 4; mi++) {
                ull wd = *(const ull*)&ws[kk][lane + 32 * mi][0];
                acc[mi][0] = ffma2(x01, wd, acc[mi][0]);
                acc[mi][1] = ffma2(x23, wd, acc[mi][1]);
            }
        }
    }
    __syncthreads();

    float u[4][4];
#pragma unroll
    for (int mi = 0; mi < 4; mi++) {
        unpack2(acc[mi][0], u[0][mi], u[1][mi]);
        unpack2(acc[mi][1], u[2][mi], u[3][mi]);
    }

#pragma unroll
    for (int j = 0; j < 4; j++) {
        int rloc = wrp * 4 + j;
        int row  = row0 + rloc;
        float mx = fmaxf(fmaxf(u[j][0], u[j][1]), fmaxf(u[j][2], u[j][3]));
#pragma unroll
        for (int o = 16; o > 0; o >>= 1)
            mx = fmaxf(mx, __shfl_xor_sync(0xffffffffu, mx, o));
        float h = 0.5f * hsum[rloc];

        if (isQ) {
#pragma unroll
            for (int mi = 0; mi < 4; mi++)
                g_Qp[row * MFEAT + lane + 32 * mi] =
                    (__expf(u[j][mi] - h - mx) + PHI_EPS) * INV_SQM;
        } else {
#pragma unroll
            for (int mi = 0; mi < 4; mi++)
                g_EK[row * MFEAT + lane + 32 * mi] = __expf(u[j][mi] - h);
            if (lane == 0) {
                int s = get_seg(segp, row);
                atomicMax(&g_segmax[s], __float_as_int(mx));
            }
        }
    }
}

// ---------------------------------------------------------------------------
// S[b][m][d] = sum_rows Kp[row][m] * V[row][d];  Ksum[b][m] = sum_rows Kp.
// Kp reconstructed: kp = fma(E, exp(-smax)/sqrt(m), eps/sqrt(m)).
// ---------------------------------------------------------------------------
__global__ void __launch_bounds__(128)
s_kernel(const float* __restrict__ V)
{
    int mt  = blockIdx.x;     // 0..7
    int b   = blockIdx.y;     // 0..63
    int tid = threadIdx.x;
    int rs = g_segstart[b], re = g_segend[b];
    float smax = __int_as_float(g_segmax[b]);
    float cA = __expf(-smax) * INV_SQM;
    float cB = PHI_EPS * INV_SQM;

    __shared__ __align__(16) float kpc[16][16];

    ull acc[8];
#pragma unroll
    for (int j = 0; j < 8; j++) acc[j] = 0ull;
    float ksum = 0.0f;

    int rr_s = tid >> 3;          // staging row 0..15
    int m2   = (tid & 7) * 2;     // staging m pair

    int row = rs;
    int nfull = (re - rs) >> 4;

    float2 e;
    if (nfull > 0)
        e = *(const float2*)(g_EK + (row + rr_s) * MFEAT + mt * 16 + m2);

    for (int c = 0; c < nfull; c++, row += 16) {
        float2 kp;
        kp.x = fmaf(e.x, cA, cB);
        kp.y = fmaf(e.y, cA, cB);
        *(float2*)&kpc[rr_s][m2] = kp;
        __syncthreads();
        if (c + 1 < nfull)
            e = *(const float2*)(g_EK + (row + 16 + rr_s) * MFEAT + mt * 16 + m2);
#pragma unroll
        for (int rr = 0; rr < 16; rr++) {
            float v = V[(row + rr) * DIM + tid];
            ull vd = pack2(v, v);
            const ulonglong2* kp2 = (const ulonglong2*)&kpc[rr][0];
#pragma unroll
            for (int j = 0; j < 4; j++) {
                ulonglong2 kk2 = kp2[j];
                acc[2 * j]     = ffma2(kk2.x, vd, acc[2 * j]);
                acc[2 * j + 1] = ffma2(kk2.y, vd, acc[2 * j + 1]);
            }
        }
        if (tid < 16) {
#pragma unroll
            for (int rr = 0; rr < 16; rr++) ksum += kpc[rr][tid];
        }
        __syncthreads();
    }

    int ntail = re - row;
    if (ntail > 0) {
        if (rr_s < ntail) {
            float2 et = *(const float2*)(g_EK + (row + rr_s) * MFEAT + mt * 16 + m2);
            float2 kp;
            kp.x = fmaf(et.x, cA, cB);
            kp.y = fmaf(et.y, cA, cB);
            *(float2*)&kpc[rr_s][m2] = kp;
        }
        __syncthreads();
        for (int rr = 0; rr < ntail; rr++) {
            float v = V[(row + rr) * DIM + tid];
            ull vd = pack2(v, v);
            const ulonglong2* kp2 = (const ulonglong2*)&kpc[rr][0];
#pragma unroll
            for (int j = 0; j < 4; j++) {
                ulonglong2 kk2 = kp2[j];
                acc[2 * j]     = ffma2(kk2.x, vd, acc[2 * j]);
                acc[2 * j + 1] = ffma2(kk2.y, vd, acc[2 * j + 1]);
            }
        }
        if (tid < 16)
            for (int rr = 0; rr < ntail; rr++) ksum += kpc[rr][tid];
    }

#pragma unroll
    for (int j = 0; j < 8; j++) {
        float a0, a1;
        unpack2(acc[j], a0, a1);
        g_S[(b * MFEAT + mt * 16 + 2 * j)     * DIM + tid] = a0;
        g_S[(b * MFEAT + mt * 16 + 2 * j + 1) * DIM + tid] = a1;
    }
    if (tid < 16)
        g_Ksum[b * MFEAT + mt * 16 + tid] = ksum;
}

// ---------------------------------------------------------------------------
// out[i][d] = (Qp[i] . S[seg][:, d]) / (Qp[i] . Ksum[seg] + eps)
// 16 rows per block. One register-tiled pass per segment-run (sorted segs ->
// runs are contiguous; non-boundary blocks do exactly one pass). S chunk
// loads double-buffered to hide L2 latency.
// ---------------------------------------------------------------------------
__global__ void __launch_bounds__(128)
out_kernel(const int* __restrict__ segp, float* __restrict__ out)
{
    __shared__ __align__(16) float qs2f[8][MFEAT][2];  // [rowpair][m][which]
    __shared__ int   segs[16];
    __shared__ float norms[16];

    int tid  = threadIdx.x;
    int lane = tid & 31;
    int wrp  = tid >> 5;
    int row0 = blockIdx.x * 16;

#pragma unroll
    for (int r = 0; r < 16; r++)
        qs2f[r >> 1][tid][r & 1] = g_Qp[(row0 + r) * MFEAT + tid];
    if (tid < 16) segs[tid] = get_seg(segp, row0 + tid);
    __syncthreads();

    // norms: warp w handles rows 4w..4w+3
#pragma unroll
    for (int rr = 0; rr < 4; rr++) {
        int r = wrp * 4 + rr;
        int s = segs[r];
        float p = 0.0f;
#pragma unroll
        for (int c = 0; c < 4; c++) {
            int m = c * 32 + lane;
            float q  = qs2f[r >> 1][m][r & 1];
            float ks = g_Ksum[s * MFEAT + m];
            p = fmaf(q, ks, p);
        }
#pragma unroll
        for (int o = 16; o > 0; o >>= 1)
            p += __shfl_xor_sync(0xffffffffu, p, o);
        if (lane == 0) norms[r] = p + NORM_EPS;
    }
    __syncthreads();

    // Process each contiguous run of equal segment with the tiled fast path.
    int rbeg = 0;
    while (rbeg < 16) {
        int s = segs[rbeg];
        int rend = rbeg + 1;
        while (rend < 16 && segs[rend] == s) rend++;

        const float* Srow = g_S + s * (MFEAT * DIM);

        ull acc2[8];
#pragma unroll
        for (int rp = 0; rp < 8; rp++) acc2[rp] = 0ull;

        // prefetch first 8-m chunk
        ull sd[8];
#pragma unroll
        for (int j = 0; j < 8; j++) {
            float sv = Srow[j * DIM + tid];
            sd[j] = pack2(sv, sv);
        }

#pragma unroll
        for (int ms = 0; ms < 16; ms++) {
            int m0 = ms * 8;
            ull sdn[8];
            if (ms < 15) {
#pragma unroll
                for (int j = 0; j < 8; j++) {
                    float sv = Srow[(m0 + 8 + j) * DIM + tid];
                    sdn[j] = pack2(sv, sv);
                }
            }
#pragma unroll
            for (int rp = 0; rp < 8; rp++) {
                const ulonglong2* qp2 = (const ulonglong2*)&qs2f[rp][m0][0];
#pragma unroll
                for (int j2 = 0; j2 < 4; j2++) {
                    ulonglong2 qq = qp2[j2];
                    acc2[rp] = ffma2(qq.x, sd[2 * j2],     acc2[rp]);
                    acc2[rp] = ffma2(qq.y, sd[2 * j2 + 1], acc2[rp]);
                }
            }
            if (ms < 15) {
#pragma unroll
                for (int j = 0; j < 8; j++) sd[j] = sdn[j];
            }
        }

#pragma unroll
        for (int rp = 0; rp < 8; rp++) {
            float a0, a1;
            unpack2(acc2[rp], a0, a1);
            int r0 = 2 * rp, r1 = 2 * rp + 1;
            if (r0 >= rbeg && r0 < rend)
                out[(row0 + r0) * DIM + tid] = a0 / norms[r0];
            if (r1 >= rbeg && r1 < rend)
                out[(row0 + r1) * DIM + tid] = a1 / norms[r1];
        }

        rbeg = rend;
    }
}

extern "C" void kernel_launch(void* const* d_in, const int* in_sizes, int n_in,
                              void* d_out, int out_size)
{
    const float* Q     = (const float*)d_in[0];
    const float* K     = (const float*)d_in[1];
    const float* V     = (const float*)d_in[2];
    const float* omega = (const float*)d_in[3];
    const int*   seg   = (const int*)d_in[4];
    float* out = (float*)d_out;

    bounds_kernel<<<NROWS / 256, 256>>>(seg);
    u_kernel<<<2 * (NROWS / 32), 256>>>(Q, K, omega, seg);
    s_kernel<<<dim3(8, NB), 128>>>(V);
    out_kernel<<<NROWS / 16, 128>>>(seg, out);
}